// round 11
// baseline (speedup 1.0000x reference)
#include <cuda_runtime.h>
#include <cuda_bf16.h>
#include <math.h>
#include <stdint.h>

typedef unsigned int u32;
typedef unsigned short u16;

#define B_     64
#define T_     128
#define EMB_   256
#define UNITS_ 1024
#define U3_    3072
#define M_     8192

#define NBLK2  128          // persistent scan blocks; block owns 8 units
// scan smem layout (bytes)
#define USTR   2064         // U row stride: 2048 data + 16 pad
#define HOFF   99072        // 48 * 2064
#define HSZ    18432        // H tile: 128 rows (2p x 64b) x 144
#define REDOFF 209664       // HOFF + 6*HSZ  (3-buffer x 2 groups)
#define SMEMSZ 215808       // REDOFF + 6144

// phase-A smem: 2 bufs x (A 256rowsx144 + B 256rowsx144)
#define ABUF   73728
#define SMEMA  147456

// ---- device-global scratch (alloc-free rule) ----
__device__ float g_xin[(size_t)M_ * U3_];             // [(t*64+b)*3072 + n]
__device__ float g_hF[2][B_ * UNITS_];                // fp32 h ping-pong [b][u]
__device__ u16 g_Hbf[2][2][B_][UNITS_];               // [sel][pass][b][u]
__device__ u16 g_Ubf[(size_t)NBLK2 * 2 * 24 * UNITS_];// [g][p][n=24][k]
__device__ u16 g_Ebf[(size_t)2 * M_ * EMB_];          // [p][m'][k] gathered emb
__device__ u16 g_Wbf[(size_t)2 * U3_ * EMB_];         // [p][n][k]
// dataflow flags: 16 producer groups (8 blocks each), monotonic counters
__device__ unsigned g_flag[16 * 32];                  // 128B apart

__device__ __forceinline__ u32 s2u(const void* p) {
    u32 r;
    asm("{ .reg .u64 t; cvta.to.shared.u64 t, %1; cvt.u32.u64 %0, t; }"
        : "=r"(r) : "l"(p));
    return r;
}
__device__ __forceinline__ void cpa_cg(u32 s, const void* g) {
    asm volatile("cp.async.cg.shared.global [%0], [%1], 16;" :: "r"(s), "l"(g));
}
__device__ __forceinline__ void cpa_ca(u32 s, const void* g) {
    asm volatile("cp.async.ca.shared.global [%0], [%1], 16;" :: "r"(s), "l"(g));
}
__device__ __forceinline__ void ldmx4(u32 addr, u32 r[4]) {
    asm volatile("ldmatrix.sync.aligned.m8n8.x4.shared.b16 {%0,%1,%2,%3}, [%4];"
                 : "=r"(r[0]), "=r"(r[1]), "=r"(r[2]), "=r"(r[3]) : "r"(addr));
}
__device__ __forceinline__ void ldmx2(u32 addr, u32 r[2]) {
    asm volatile("ldmatrix.sync.aligned.m8n8.x2.shared.b16 {%0,%1}, [%2];"
                 : "=r"(r[0]), "=r"(r[1]) : "r"(addr));
}
__device__ __forceinline__ void mma16816(float c[4], const u32 a[4], const u32 b[2]) {
    asm volatile("mma.sync.aligned.m16n8k16.row.col.f32.bf16.bf16.f32 "
                 "{%0,%1,%2,%3}, {%4,%5,%6,%7}, {%8,%9}, {%0,%1,%2,%3};"
                 : "+f"(c[0]), "+f"(c[1]), "+f"(c[2]), "+f"(c[3])
                 : "r"(a[0]), "r"(a[1]), "r"(a[2]), "r"(a[3]),
                   "r"(b[0]), "r"(b[1]));
}
__device__ __forceinline__ void flag_arrive(unsigned* p) {
    unsigned old;
    asm volatile("atom.add.acq_rel.gpu.global.u32 %0, [%1], 1;"
                 : "=r"(old) : "l"(p) : "memory");
}
__device__ __forceinline__ void wait_flag(const unsigned* p, unsigned tgt) {
    unsigned v;
    do {
        asm volatile("ld.acquire.gpu.global.u32 %0, [%1];" : "=r"(v) : "l"(p));
    } while (v < tgt);
}

// ---------------------------------------------------------------------------
__global__ void init_h_tc(const float* __restrict__ hidden) {
    int idx = blockIdx.x * 256 + threadIdx.x;   // 65536
    if (idx < 16 * 32) g_flag[idx] = 0;
    int b = idx >> 10, u = idx & 1023;
    float v = hidden[idx];
    g_hF[0][idx] = v;
    __nv_bfloat16 hi = __float2bfloat16(v);
    __nv_bfloat16 lo = __float2bfloat16(v - __bfloat162float(hi));
    g_Hbf[0][0][b][u] = *(u16*)&hi;
    g_Hbf[0][1][b][u] = *(u16*)&lo;
}

// U^T per-block rows: g_Ubf[((g*2+p)*24 + n)*1024 + k], n = gate*8 + ul
__global__ void uprep_bf(const float* __restrict__ U) {
    size_t idx = (size_t)blockIdx.x * 256 + threadIdx.x;  // 6,291,456
    int k = idx & 1023;
    int rest = (int)(idx >> 10);
    int n = rest % 24;
    int gp = rest / 24;
    int p = gp & 1, g = gp >> 1;
    int s = n >> 3, ul = n & 7;
    float v = U[(size_t)k * U3_ + s * UNITS_ + g * 8 + ul];
    __nv_bfloat16 hi = __float2bfloat16(v);
    __nv_bfloat16 w = p ? __float2bfloat16(v - __bfloat162float(hi)) : hi;
    g_Ubf[idx] = *(u16*)&w;
}

// W -> bf16 hi/lo, k-major per n: g_Wbf[(p*3072+n)*256+k]
__global__ void wprep_bf(const float* __restrict__ W) {
    int gid = blockIdx.x * 256 + threadIdx.x;   // 1,572,864
    int k = gid & 255;
    int n = (gid >> 8) % U3_;
    int p = gid / (U3_ * 256);
    float v = W[(size_t)k * U3_ + n];
    __nv_bfloat16 hi = __float2bfloat16(v);
    __nv_bfloat16 w = p ? __float2bfloat16(v - __bfloat162float(hi)) : hi;
    g_Wbf[gid] = *(u16*)&w;
}

// gathered embedding -> bf16 hi/lo, m' = t*64+b: g_Ebf[(p*8192+m)*256+k]
__global__ void embprep_bf(const int* __restrict__ x,
                           const float* __restrict__ E) {
    int gid = blockIdx.x * 256 + threadIdx.x;   // 2,097,152
    int k = gid & 255, m = gid >> 8;
    int b = m & 63, t = m >> 6;
    float v = E[(size_t)x[b * T_ + t] * EMB_ + k];
    __nv_bfloat16 hi = __float2bfloat16(v);
    __nv_bfloat16 lo = __float2bfloat16(v - __bfloat162float(hi));
    g_Ebf[gid] = *(u16*)&hi;
    g_Ebf[(size_t)M_ * EMB_ + gid] = *(u16*)&lo;
}

// ---------------------------------------------------------------------------
// Phase A (tensor): xin = emb @ W + b0 via split-bf16 mma.sync.
// ---------------------------------------------------------------------------
__global__ void __launch_bounds__(256, 1)
xin_mma(const float* __restrict__ bias) {
    extern __shared__ char sm[];
    const u32 sb = s2u(sm);
    const int tid = threadIdx.x;
    const int w = tid >> 5, lane = tid & 31;
    const int wm = w >> 2, wn = w & 3;
    const int nt0 = blockIdx.x * 128;
    const int mt0 = blockIdx.y * 128;

    float acc[4][4][4];
#pragma unroll
    for (int a = 0; a < 4; a++)
#pragma unroll
        for (int b = 0; b < 4; b++)
#pragma unroll
            for (int c = 0; c < 4; c++) acc[a][b][c] = 0.0f;

    const char* ebase = (const char*)g_Ebf;
    const char* wbase = (const char*)g_Wbf;

#define STAGE_A(cc, buf)                                                      \
    do {                                                                      \
        const int c_ = (cc);                                                  \
        const u32 d0 = sb + (buf) * ABUF;                                     \
        _Pragma("unroll")                                                     \
        for (int j = 0; j < 8; j++) {                                         \
            int o = tid + j * 256;                                            \
            int p = o >> 10, row = (o >> 3) & 127, seg = o & 7;               \
            cpa_cg(d0 + (p * 128 + row) * 144 + seg * 16,                     \
                   ebase + ((size_t)(p * M_ + mt0 + row)) * 512 +             \
                       c_ * 128 + seg * 16);                                  \
        }                                                                     \
        _Pragma("unroll")                                                     \
        for (int j = 0; j < 8; j++) {                                         \
            int o = tid + j * 256;                                            \
            int p = o >> 10, row = (o >> 3) & 127, seg = o & 7;               \
            cpa_cg(d0 + 36864 + (p * 128 + row) * 144 + seg * 16,             \
                   wbase + ((size_t)(p * U3_ + nt0 + row)) * 512 +            \
                       c_ * 128 + seg * 16);                                  \
        }                                                                     \
        asm volatile("cp.async.commit_group;");                               \
    } while (0)

    STAGE_A(0, 0);

    const u32 a_off = (u32)((wm * 64 + (lane & 15)) * 144 + (lane >> 4) * 16);
    const u32 b_off = (u32)(36864 + (wn * 32 + (lane >> 4) * 8 + (lane & 7)) * 144 +
                            ((lane >> 3) & 1) * 16);

    for (int c = 0; c < 4; c++) {
        if (c < 3) {
            asm volatile("cp.async.wait_group 0;");
            __syncthreads();
            STAGE_A(c + 1, (c + 1) & 1);
        } else {
            asm volatile("cp.async.wait_group 0;");
            __syncthreads();
        }
        const u32 d0 = sb + (c & 1) * ABUF;
#pragma unroll
        for (int ks = 0; ks < 4; ks++) {
            u32 ah[4][4], al[4][4], bh[2][4], bl[2][4];
#pragma unroll
            for (int ms = 0; ms < 4; ms++) {
                ldmx4(d0 + a_off + ms * 16 * 144 + ks * 32, ah[ms]);
                ldmx4(d0 + a_off + (128 + ms * 16) * 144 + ks * 32, al[ms]);
            }
#pragma unroll
            for (int np = 0; np < 2; np++) {
                ldmx4(d0 + b_off + np * 16 * 144 + ks * 32, bh[np]);
                ldmx4(d0 + b_off + (128 + np * 16) * 144 + ks * 32, bl[np]);
            }
#pragma unroll
            for (int ms = 0; ms < 4; ms++)
#pragma unroll
                for (int np = 0; np < 2; np++)
#pragma unroll
                    for (int hf = 0; hf < 2; hf++) {
                        float* ac = acc[ms][np * 2 + hf];
                        mma16816(ac, ah[ms], bh[np] + hf * 2);
                        mma16816(ac, ah[ms], bl[np] + hf * 2);
                        mma16816(ac, al[ms], bh[np] + hf * 2);
                    }
        }
        __syncthreads();
    }
#undef STAGE_A

    float bn[4][2];
#pragma unroll
    for (int ns = 0; ns < 4; ns++)
#pragma unroll
        for (int j = 0; j < 2; j++)
            bn[ns][j] = bias[nt0 + wn * 32 + ns * 8 + 2 * (lane & 3) + j];

#pragma unroll
    for (int ms = 0; ms < 4; ms++)
#pragma unroll
        for (int ns = 0; ns < 4; ns++)
#pragma unroll
            for (int i = 0; i < 2; i++)
#pragma unroll
                for (int j = 0; j < 2; j++) {
                    int m = mt0 + wm * 64 + ms * 16 + (lane >> 2) + 8 * i;
                    int n = nt0 + wn * 32 + ns * 8 + 2 * (lane & 3) + j;
                    g_xin[(size_t)m * U3_ + n] = acc[ms][ns][2 * i + j] + bn[ns][j];
                }
}

// ---------------------------------------------------------------------------
// Persistent scan: 128 blocks x 256 thr, 1 block/SM. Block g owns 8 units.
// U resident in smem. Cross-block sync = per-chunk dataflow flags:
// 16 producer groups; staging chunk cc at step t waits flag[cc],flag[8+cc]>=8t.
// ---------------------------------------------------------------------------
__global__ void __launch_bounds__(256, 1)
gru_scan(const float* __restrict__ bias, float* __restrict__ out) {
    extern __shared__ char sm[];
    const u32 sb = s2u(sm);
    const int tid = threadIdx.x;
    const int w = tid >> 5, lane = tid & 31;
    const int mt = w & 3, gr = w >> 2;
    const int g = blockIdx.x;

    // ---- stage U slice once ----
    {
        const char* usrc = (const char*)g_Ubf + (size_t)g * 98304;
#pragma unroll
        for (int j = 0; j < 24; j++) {
            int o = tid + j * 256;
            int row = o >> 7, seg = o & 127;
            cpa_ca(sb + row * USTR + seg * 16, usrc + (size_t)o * 16);
        }
        asm volatile("cp.async.commit_group;");
    }

    const u32 a_off = (u32)((mt * 16 + (lane & 15)) * 144 + (lane >> 4) * 16);
    const u32 b01 = sb + (u32)(((lane >> 4) * 8 + (lane & 7)) * USTR +
                               ((lane >> 3) & 1) * 16);
    const u32 b2  = sb + (u32)((16 + (lane & 7)) * USTR + ((lane >> 3) & 1) * 16);

    const int u0e = g * 8 + 2 * (lane & 3);
    const int b_e = mt * 16 + (lane >> 2) + 8 * gr;
    const float bz0 = bias[U3_ + u0e],              bz1 = bias[U3_ + u0e + 1];
    const float br0 = bias[U3_ + UNITS_ + u0e],     br1 = bias[U3_ + UNITS_ + u0e + 1];
    const float bh0 = bias[U3_ + 2 * UNITS_ + u0e], bh1 = bias[U3_ + 2 * UNITS_ + u0e + 1];

    float* red = (float*)(sm + REDOFF);

    for (int t = 0; t < T_; t++) {
        const int cur = t & 1, nxt = cur ^ 1;
        const char* hsrc = (const char*)&g_Hbf[cur][0][0][0];
        const unsigned tgt = (unsigned)(8 * t);

        const float* xrow = &g_xin[(size_t)(t * 64 + b_e) * U3_ + u0e];
        float xz0 = __ldg(xrow), xz1 = __ldg(xrow + 1);
        float xr0 = __ldg(xrow + UNITS_), xr1 = __ldg(xrow + UNITS_ + 1);
        float xh0 = __ldg(xrow + 2 * UNITS_), xh1 = __ldg(xrow + 2 * UNITS_ + 1);
        float hp0 = g_hF[cur][b_e * UNITS_ + u0e];
        float hp1 = g_hF[cur][b_e * UNITS_ + u0e + 1];

        float acc[3][4];
#pragma unroll
        for (int i = 0; i < 3; i++)
#pragma unroll
            for (int j = 0; j < 4; j++) acc[i][j] = 0.0f;

#define STAGE_H(cc, buf)                                                      \
    do {                                                                      \
        _Pragma("unroll")                                                     \
        for (int j = 0; j < 8; j++) {                                         \
            int o = tid + j * 256;                                            \
            int grs = o >> 10, r = (o >> 3) & 127, seg = o & 7;               \
            int cab = grs * 8 + (cc);                                         \
            cpa_cg(sb + HOFF + (grs * 3 + (buf)) * HSZ + r * 144 + seg * 16,  \
                   hsrc + ((size_t)r * 1024 + cab * 64) * 2 + seg * 16);      \
        }                                                                     \
        asm volatile("cp.async.commit_group;");                               \
    } while (0)

#define WAIT_FLAGS(cc)                                                        \
    do {                                                                      \
        if (tgt) {                                                            \
            wait_flag(&g_flag[(cc) * 32], tgt);                               \
            wait_flag(&g_flag[(8 + (cc)) * 32], tgt);                         \
        }                                                                     \
    } while (0)

        WAIT_FLAGS(0);
        STAGE_H(0, 0);
        WAIT_FLAGS(1);
        STAGE_H(1, 1);

        for (int c = 0; c < 8; c++) {
            if (c < 7) asm volatile("cp.async.wait_group 1;");
            else       asm volatile("cp.async.wait_group 0;");
            __syncthreads();

            const int cab = gr * 8 + c;
            const u32 abase = sb + HOFF + (u32)((gr * 3 + c % 3) * HSZ) + a_off;
            const u32 koff = (u32)(cab * 128);
#pragma unroll
            for (int ks = 0; ks < 4; ks++) {
                u32 ah[4], al[4], b4h[4], b4l[4], b2h[2], b2l[2];
                const u32 ko = koff + ks * 32;
                ldmx4(abase + ks * 32, ah);
                ldmx4(abase + 9216 + ks * 32, al);
                ldmx4(b01 + ko, b4h);
                ldmx4(b01 + 24 * USTR + ko, b4l);
                ldmx2(b2 + ko, b2h);
                ldmx2(b2 + 24 * USTR + ko, b2l);
                mma16816(acc[0], ah, b4h);     mma16816(acc[1], ah, b4h + 2);
                mma16816(acc[2], ah, b2h);
                mma16816(acc[0], ah, b4l);     mma16816(acc[1], ah, b4l + 2);
                mma16816(acc[2], ah, b2l);
                mma16816(acc[0], al, b4h);     mma16816(acc[1], al, b4h + 2);
                mma16816(acc[2], al, b2h);
            }

            if (c < 6) {
                WAIT_FLAGS(c + 2);
                STAGE_H(c + 2, (c + 2) % 3);
            }
        }
#undef STAGE_H
#undef WAIT_FLAGS

        // ---- symmetric partial exchange ----
        const int oi = gr ^ 1;
#pragma unroll
        for (int i = 0; i < 3; i++)
#pragma unroll
            for (int j = 0; j < 2; j++)
                red[(w * 32 + lane) * 6 + i * 2 + j] = acc[i][2 * oi + j];
        __syncthreads();
        const int pw = (gr ^ 1) * 4 + mt;
#pragma unroll
        for (int i = 0; i < 3; i++)
#pragma unroll
            for (int j = 0; j < 2; j++)
                acc[i][2 * gr + j] += red[(pw * 32 + lane) * 6 + i * 2 + j];

        // ---- epilogue ----
#pragma unroll
        for (int j = 0; j < 2; j++) {
            const int u = u0e + j;
            const int r = 2 * gr + j;
            const float xz = j ? xz1 : xz0, xr = j ? xr1 : xr0, xh = j ? xh1 : xh0;
            const float hprev = j ? hp1 : hp0;
            const float bz_ = j ? bz1 : bz0, br_ = j ? br1 : br0, bh_ = j ? bh1 : bh0;

            float z = 1.f / (1.f + expf(-(xz + acc[0][r] + bz_)));
            float rr = 1.f / (1.f + expf(-(xr + acc[1][r] + br_)));
            float hh = tanhf(xh + rr * (acc[2][r] + bh_));
            float hn = z * hprev + (1.f - z) * hh;

            g_hF[nxt][b_e * UNITS_ + u] = hn;
            out[(size_t)(b_e * T_ + t) * UNITS_ + u] = hn;
            __nv_bfloat16 hi = __float2bfloat16(hn);
            __nv_bfloat16 lo = __float2bfloat16(hn - __bfloat162float(hi));
            g_Hbf[nxt][0][b_e][u] = *(u16*)&hi;
            g_Hbf[nxt][1][b_e][u] = *(u16*)&lo;
            if (t == T_ - 1)
                out[(size_t)M_ * UNITS_ + (size_t)b_e * UNITS_ + u] = hn;
        }

        // ---- arrive: h for step t+1 published ----
        __syncthreads();
        if (tid == 0) flag_arrive(&g_flag[(g >> 3) * 32]);
    }
}

extern "C" void kernel_launch(void* const* d_in, const int* in_sizes, int n_in,
                              void* d_out, int out_size) {
    const int*   x      = (const int*)d_in[0];
    const float* hidden = (const float*)d_in[1];
    const float* E      = (const float*)d_in[2];
    const float* W      = (const float*)d_in[3];
    const float* Umat   = (const float*)d_in[4];
    const float* bias   = (const float*)d_in[5];
    float* out = (float*)d_out;

    cudaFuncSetAttribute(gru_scan,
                         cudaFuncAttributeMaxDynamicSharedMemorySize, SMEMSZ);
    cudaFuncSetAttribute(xin_mma,
                         cudaFuncAttributeMaxDynamicSharedMemorySize, SMEMA);

    init_h_tc<<<256, 256>>>(hidden);
    uprep_bf<<<24576, 256>>>(Umat);
    wprep_bf<<<6144, 256>>>(W);
    embprep_bf<<<8192, 256>>>(x, E);

    dim3 gridA(U3_ / 128, M_ / 128);   // (24, 64)
    xin_mma<<<gridA, 256, SMEMA>>>(bias);

    gru_scan<<<NBLK2, 256, SMEMSZ>>>(bias, out);
}

// round 12
// speedup vs baseline: 1.3690x; 1.3690x over previous
#include <cuda_runtime.h>
#include <cuda_bf16.h>
#include <math.h>
#include <stdint.h>

typedef unsigned int u32;
typedef unsigned short u16;

#define B_     64
#define T_     128
#define EMB_   256
#define UNITS_ 1024
#define U3_    3072
#define M_     8192

#define NBLK2  128          // persistent scan blocks; block owns 8 units
// scan smem layout (bytes)
#define USTR   2064         // U row stride: 2048 data + 16 pad
#define HOFF   99072        // 48 * 2064
#define HSZ    18432        // H tile: 128 rows (2p x 64b) x 144
#define REDOFF 209664       // HOFF + 6*HSZ  (3-buffer x 2 groups)
#define SMEMSZ 215808       // REDOFF + 6144

// phase-A smem: 2 bufs x (A 256rowsx144 + B 256rowsx144)
#define ABUF   73728
#define SMEMA  147456

// ---- device-global scratch (alloc-free rule) ----
__device__ float g_xin[(size_t)M_ * U3_];             // [(t*64+b)*3072 + n]
__device__ float g_hF[2][B_ * UNITS_];                // fp32 h ping-pong [b][u]
__device__ u16 g_Hbf[2][2][B_][UNITS_];               // [sel][pass][b][u]
__device__ u16 g_Ubf[(size_t)NBLK2 * 2 * 24 * UNITS_];// [g][p][n=24][k]
__device__ u16 g_Ebf[(size_t)2 * M_ * EMB_];          // [p][m'][k] gathered emb
__device__ u16 g_Wbf[(size_t)2 * U3_ * EMB_];         // [p][n][k]
// flat barrier state (monotonic counters)
__device__ unsigned g_barcnt;
__device__ unsigned g_bargen;

__device__ __forceinline__ u32 s2u(const void* p) {
    u32 r;
    asm("{ .reg .u64 t; cvta.to.shared.u64 t, %1; cvt.u32.u64 %0, t; }"
        : "=r"(r) : "l"(p));
    return r;
}
__device__ __forceinline__ void cpa_cg(u32 s, const void* g) {
    asm volatile("cp.async.cg.shared.global [%0], [%1], 16;" :: "r"(s), "l"(g));
}
__device__ __forceinline__ void cpa_ca(u32 s, const void* g) {
    asm volatile("cp.async.ca.shared.global [%0], [%1], 16;" :: "r"(s), "l"(g));
}
__device__ __forceinline__ void ldmx4(u32 addr, u32 r[4]) {
    asm volatile("ldmatrix.sync.aligned.m8n8.x4.shared.b16 {%0,%1,%2,%3}, [%4];"
                 : "=r"(r[0]), "=r"(r[1]), "=r"(r[2]), "=r"(r[3]) : "r"(addr));
}
__device__ __forceinline__ void ldmx2(u32 addr, u32 r[2]) {
    asm volatile("ldmatrix.sync.aligned.m8n8.x2.shared.b16 {%0,%1}, [%2];"
                 : "=r"(r[0]), "=r"(r[1]) : "r"(addr));
}
__device__ __forceinline__ void mma16816(float c[4], const u32 a[4], const u32 b[2]) {
    asm volatile("mma.sync.aligned.m16n8k16.row.col.f32.bf16.bf16.f32 "
                 "{%0,%1,%2,%3}, {%4,%5,%6,%7}, {%8,%9}, {%0,%1,%2,%3};"
                 : "+f"(c[0]), "+f"(c[1]), "+f"(c[2]), "+f"(c[3])
                 : "r"(a[0]), "r"(a[1]), "r"(a[2]), "r"(a[3]),
                   "r"(b[0]), "r"(b[1]));
}

// ---------------------------------------------------------------------------
__global__ void init_h_tc(const float* __restrict__ hidden) {
    int idx = blockIdx.x * 256 + threadIdx.x;   // 65536
    if (idx == 0) { g_barcnt = 0; g_bargen = 0; }
    int b = idx >> 10, u = idx & 1023;
    float v = hidden[idx];
    g_hF[0][idx] = v;
    __nv_bfloat16 hi = __float2bfloat16(v);
    __nv_bfloat16 lo = __float2bfloat16(v - __bfloat162float(hi));
    g_Hbf[0][0][b][u] = *(u16*)&hi;
    g_Hbf[0][1][b][u] = *(u16*)&lo;
}

// U^T per-block rows: g_Ubf[((g*2+p)*24 + n)*1024 + k], n = gate*8 + ul
__global__ void uprep_bf(const float* __restrict__ U) {
    size_t idx = (size_t)blockIdx.x * 256 + threadIdx.x;  // 6,291,456
    int k = idx & 1023;
    int rest = (int)(idx >> 10);
    int n = rest % 24;
    int gp = rest / 24;
    int p = gp & 1, g = gp >> 1;
    int s = n >> 3, ul = n & 7;
    float v = U[(size_t)k * U3_ + s * UNITS_ + g * 8 + ul];
    __nv_bfloat16 hi = __float2bfloat16(v);
    __nv_bfloat16 w = p ? __float2bfloat16(v - __bfloat162float(hi)) : hi;
    g_Ubf[idx] = *(u16*)&w;
}

// W -> bf16 hi/lo, k-major per n: g_Wbf[(p*3072+n)*256+k]
__global__ void wprep_bf(const float* __restrict__ W) {
    int gid = blockIdx.x * 256 + threadIdx.x;   // 1,572,864
    int k = gid & 255;
    int n = (gid >> 8) % U3_;
    int p = gid / (U3_ * 256);
    float v = W[(size_t)k * U3_ + n];
    __nv_bfloat16 hi = __float2bfloat16(v);
    __nv_bfloat16 w = p ? __float2bfloat16(v - __bfloat162float(hi)) : hi;
    g_Wbf[gid] = *(u16*)&w;
}

// gathered embedding -> bf16 hi/lo, m' = t*64+b: g_Ebf[(p*8192+m)*256+k]
__global__ void embprep_bf(const int* __restrict__ x,
                           const float* __restrict__ E) {
    int gid = blockIdx.x * 256 + threadIdx.x;   // 2,097,152
    int k = gid & 255, m = gid >> 8;
    int b = m & 63, t = m >> 6;
    float v = E[(size_t)x[b * T_ + t] * EMB_ + k];
    __nv_bfloat16 hi = __float2bfloat16(v);
    __nv_bfloat16 lo = __float2bfloat16(v - __bfloat162float(hi));
    g_Ebf[gid] = *(u16*)&hi;
    g_Ebf[(size_t)M_ * EMB_ + gid] = *(u16*)&lo;
}

// ---------------------------------------------------------------------------
// Phase A (tensor): xin = emb @ W + b0 via split-bf16 mma.sync.
// ---------------------------------------------------------------------------
__global__ void __launch_bounds__(256, 1)
xin_mma(const float* __restrict__ bias) {
    extern __shared__ char sm[];
    const u32 sb = s2u(sm);
    const int tid = threadIdx.x;
    const int w = tid >> 5, lane = tid & 31;
    const int wm = w >> 2, wn = w & 3;
    const int nt0 = blockIdx.x * 128;
    const int mt0 = blockIdx.y * 128;

    float acc[4][4][4];
#pragma unroll
    for (int a = 0; a < 4; a++)
#pragma unroll
        for (int b = 0; b < 4; b++)
#pragma unroll
            for (int c = 0; c < 4; c++) acc[a][b][c] = 0.0f;

    const char* ebase = (const char*)g_Ebf;
    const char* wbase = (const char*)g_Wbf;

#define STAGE_A(cc, buf)                                                      \
    do {                                                                      \
        const int c_ = (cc);                                                  \
        const u32 d0 = sb + (buf) * ABUF;                                     \
        _Pragma("unroll")                                                     \
        for (int j = 0; j < 8; j++) {                                         \
            int o = tid + j * 256;                                            \
            int p = o >> 10, row = (o >> 3) & 127, seg = o & 7;               \
            cpa_cg(d0 + (p * 128 + row) * 144 + seg * 16,                     \
                   ebase + ((size_t)(p * M_ + mt0 + row)) * 512 +             \
                       c_ * 128 + seg * 16);                                  \
        }                                                                     \
        _Pragma("unroll")                                                     \
        for (int j = 0; j < 8; j++) {                                         \
            int o = tid + j * 256;                                            \
            int p = o >> 10, row = (o >> 3) & 127, seg = o & 7;               \
            cpa_cg(d0 + 36864 + (p * 128 + row) * 144 + seg * 16,             \
                   wbase + ((size_t)(p * U3_ + nt0 + row)) * 512 +            \
                       c_ * 128 + seg * 16);                                  \
        }                                                                     \
        asm volatile("cp.async.commit_group;");                               \
    } while (0)

    STAGE_A(0, 0);

    const u32 a_off = (u32)((wm * 64 + (lane & 15)) * 144 + (lane >> 4) * 16);
    const u32 b_off = (u32)(36864 + (wn * 32 + (lane >> 4) * 8 + (lane & 7)) * 144 +
                            ((lane >> 3) & 1) * 16);

    for (int c = 0; c < 4; c++) {
        if (c < 3) {
            asm volatile("cp.async.wait_group 0;");
            __syncthreads();
            STAGE_A(c + 1, (c + 1) & 1);
        } else {
            asm volatile("cp.async.wait_group 0;");
            __syncthreads();
        }
        const u32 d0 = sb + (c & 1) * ABUF;
#pragma unroll
        for (int ks = 0; ks < 4; ks++) {
            u32 ah[4][4], al[4][4], bh[2][4], bl[2][4];
#pragma unroll
            for (int ms = 0; ms < 4; ms++) {
                ldmx4(d0 + a_off + ms * 16 * 144 + ks * 32, ah[ms]);
                ldmx4(d0 + a_off + (128 + ms * 16) * 144 + ks * 32, al[ms]);
            }
#pragma unroll
            for (int np = 0; np < 2; np++) {
                ldmx4(d0 + b_off + np * 16 * 144 + ks * 32, bh[np]);
                ldmx4(d0 + b_off + (128 + np * 16) * 144 + ks * 32, bl[np]);
            }
#pragma unroll
            for (int ms = 0; ms < 4; ms++)
#pragma unroll
                for (int np = 0; np < 2; np++)
#pragma unroll
                    for (int hf = 0; hf < 2; hf++) {
                        float* ac = acc[ms][np * 2 + hf];
                        mma16816(ac, ah[ms], bh[np] + hf * 2);
                        mma16816(ac, ah[ms], bl[np] + hf * 2);
                        mma16816(ac, al[ms], bh[np] + hf * 2);
                    }
        }
        __syncthreads();
    }
#undef STAGE_A

    float bn[4][2];
#pragma unroll
    for (int ns = 0; ns < 4; ns++)
#pragma unroll
        for (int j = 0; j < 2; j++)
            bn[ns][j] = bias[nt0 + wn * 32 + ns * 8 + 2 * (lane & 3) + j];

#pragma unroll
    for (int ms = 0; ms < 4; ms++)
#pragma unroll
        for (int ns = 0; ns < 4; ns++)
#pragma unroll
            for (int i = 0; i < 2; i++)
#pragma unroll
                for (int j = 0; j < 2; j++) {
                    int m = mt0 + wm * 64 + ms * 16 + (lane >> 2) + 8 * i;
                    int n = nt0 + wn * 32 + ns * 8 + 2 * (lane & 3) + j;
                    g_xin[(size_t)m * U3_ + n] = acc[ms][ns][2 * i + j] + bn[ns][j];
                }
}

// ---------------------------------------------------------------------------
// Persistent scan: 128 blocks x 256 thr, 1 block/SM. Block g owns 8 units.
// U resident in smem. Flat monotonic barrier, acq_rel arrival (no membar).
// ---------------------------------------------------------------------------
__global__ void __launch_bounds__(256, 1)
gru_scan(const float* __restrict__ bias, float* __restrict__ out) {
    extern __shared__ char sm[];
    const u32 sb = s2u(sm);
    const int tid = threadIdx.x;
    const int w = tid >> 5, lane = tid & 31;
    const int mt = w & 3, gr = w >> 2;
    const int g = blockIdx.x;

    // ---- stage U slice once ----
    {
        const char* usrc = (const char*)g_Ubf + (size_t)g * 98304;
#pragma unroll
        for (int j = 0; j < 24; j++) {
            int o = tid + j * 256;
            int row = o >> 7, seg = o & 127;
            cpa_ca(sb + row * USTR + seg * 16, usrc + (size_t)o * 16);
        }
        asm volatile("cp.async.commit_group;");
    }

    const u32 a_off = (u32)((mt * 16 + (lane & 15)) * 144 + (lane >> 4) * 16);
    const u32 b01 = sb + (u32)(((lane >> 4) * 8 + (lane & 7)) * USTR +
                               ((lane >> 3) & 1) * 16);
    const u32 b2  = sb + (u32)((16 + (lane & 7)) * USTR + ((lane >> 3) & 1) * 16);

    const int u0e = g * 8 + 2 * (lane & 3);
    const int b_e = mt * 16 + (lane >> 2) + 8 * gr;
    const float bz0 = bias[U3_ + u0e],              bz1 = bias[U3_ + u0e + 1];
    const float br0 = bias[U3_ + UNITS_ + u0e],     br1 = bias[U3_ + UNITS_ + u0e + 1];
    const float bh0 = bias[U3_ + 2 * UNITS_ + u0e], bh1 = bias[U3_ + 2 * UNITS_ + u0e + 1];

    float* red = (float*)(sm + REDOFF);

    for (int t = 0; t < T_; t++) {
        const int cur = t & 1, nxt = cur ^ 1;
        const char* hsrc = (const char*)&g_Hbf[cur][0][0][0];

        const float* xrow = &g_xin[(size_t)(t * 64 + b_e) * U3_ + u0e];
        float xz0 = __ldg(xrow), xz1 = __ldg(xrow + 1);
        float xr0 = __ldg(xrow + UNITS_), xr1 = __ldg(xrow + UNITS_ + 1);
        float xh0 = __ldg(xrow + 2 * UNITS_), xh1 = __ldg(xrow + 2 * UNITS_ + 1);
        float hp0 = g_hF[cur][b_e * UNITS_ + u0e];
        float hp1 = g_hF[cur][b_e * UNITS_ + u0e + 1];

        float acc[3][4];
#pragma unroll
        for (int i = 0; i < 3; i++)
#pragma unroll
            for (int j = 0; j < 4; j++) acc[i][j] = 0.0f;

#define STAGE_H(cc, buf)                                                      \
    do {                                                                      \
        _Pragma("unroll")                                                     \
        for (int j = 0; j < 8; j++) {                                         \
            int o = tid + j * 256;                                            \
            int grs = o >> 10, r = (o >> 3) & 127, seg = o & 7;               \
            int cab = grs * 8 + (cc);                                         \
            cpa_cg(sb + HOFF + (grs * 3 + (buf)) * HSZ + r * 144 + seg * 16,  \
                   hsrc + ((size_t)r * 1024 + cab * 64) * 2 + seg * 16);      \
        }                                                                     \
        asm volatile("cp.async.commit_group;");                               \
    } while (0)

        STAGE_H(0, 0);
        STAGE_H(1, 1);

        for (int c = 0; c < 8; c++) {
            if (c < 7) asm volatile("cp.async.wait_group 1;");
            else       asm volatile("cp.async.wait_group 0;");
            __syncthreads();
            if (c < 6) STAGE_H(c + 2, (c + 2) % 3);

            const int cab = gr * 8 + c;
            const u32 abase = sb + HOFF + (u32)((gr * 3 + c % 3) * HSZ) + a_off;
            const u32 koff = (u32)(cab * 128);
#pragma unroll
            for (int ks = 0; ks < 4; ks++) {
                u32 ah[4], al[4], b4h[4], b4l[4], b2h[2], b2l[2];
                const u32 ko = koff + ks * 32;
                ldmx4(abase + ks * 32, ah);
                ldmx4(abase + 9216 + ks * 32, al);
                ldmx4(b01 + ko, b4h);
                ldmx4(b01 + 24 * USTR + ko, b4l);
                ldmx2(b2 + ko, b2h);
                ldmx2(b2 + 24 * USTR + ko, b2l);
                mma16816(acc[0], ah, b4h);     mma16816(acc[1], ah, b4h + 2);
                mma16816(acc[2], ah, b2h);
                mma16816(acc[0], ah, b4l);     mma16816(acc[1], ah, b4l + 2);
                mma16816(acc[2], ah, b2l);
                mma16816(acc[0], al, b4h);     mma16816(acc[1], al, b4h + 2);
                mma16816(acc[2], al, b2h);
            }
        }
#undef STAGE_H

        // ---- symmetric partial exchange ----
        const int oi = gr ^ 1;
#pragma unroll
        for (int i = 0; i < 3; i++)
#pragma unroll
            for (int j = 0; j < 2; j++)
                red[(w * 32 + lane) * 6 + i * 2 + j] = acc[i][2 * oi + j];
        __syncthreads();
        const int pw = (gr ^ 1) * 4 + mt;
#pragma unroll
        for (int i = 0; i < 3; i++)
#pragma unroll
            for (int j = 0; j < 2; j++)
                acc[i][2 * gr + j] += red[(pw * 32 + lane) * 6 + i * 2 + j];

        // ---- epilogue ----
#pragma unroll
        for (int j = 0; j < 2; j++) {
            const int u = u0e + j;
            const int r = 2 * gr + j;
            const float xz = j ? xz1 : xz0, xr = j ? xr1 : xr0, xh = j ? xh1 : xh0;
            const float hprev = j ? hp1 : hp0;
            const float bz_ = j ? bz1 : bz0, br_ = j ? br1 : br0, bh_ = j ? bh1 : bh0;

            float z = 1.f / (1.f + expf(-(xz + acc[0][r] + bz_)));
            float rr = 1.f / (1.f + expf(-(xr + acc[1][r] + br_)));
            float hh = tanhf(xh + rr * (acc[2][r] + bh_));
            float hn = z * hprev + (1.f - z) * hh;

            g_hF[nxt][b_e * UNITS_ + u] = hn;
            out[(size_t)(b_e * T_ + t) * UNITS_ + u] = hn;
            __nv_bfloat16 hi = __float2bfloat16(hn);
            __nv_bfloat16 lo = __float2bfloat16(hn - __bfloat162float(hi));
            g_Hbf[nxt][0][b_e][u] = *(u16*)&hi;
            g_Hbf[nxt][1][b_e][u] = *(u16*)&lo;
            if (t == T_ - 1)
                out[(size_t)M_ * UNITS_ + (size_t)b_e * UNITS_ + u] = hn;
        }

        // ---- flat grid barrier (monotonic, acq_rel arrival, no membar) ----
        __syncthreads();
        if (tid == 0) {
            unsigned old;
            asm volatile("atom.add.acq_rel.gpu.global.u32 %0, [%1], 1;"
                         : "=r"(old) : "l"(&g_barcnt) : "memory");
            if (old == (unsigned)(NBLK2 * (t + 1) - 1)) {
                asm volatile("st.release.gpu.global.u32 [%0], %1;"
                             :: "l"(&g_bargen), "r"((unsigned)(t + 1)) : "memory");
            } else {
                unsigned v;
                do {
                    asm volatile("ld.acquire.gpu.global.u32 %0, [%1];"
                                 : "=r"(v) : "l"(&g_bargen));
                } while (v < (unsigned)(t + 1));
            }
        }
        __syncthreads();
    }
}

extern "C" void kernel_launch(void* const* d_in, const int* in_sizes, int n_in,
                              void* d_out, int out_size) {
    const int*   x      = (const int*)d_in[0];
    const float* hidden = (const float*)d_in[1];
    const float* E      = (const float*)d_in[2];
    const float* W      = (const float*)d_in[3];
    const float* Umat   = (const float*)d_in[4];
    const float* bias   = (const float*)d_in[5];
    float* out = (float*)d_out;

    cudaFuncSetAttribute(gru_scan,
                         cudaFuncAttributeMaxDynamicSharedMemorySize, SMEMSZ);
    cudaFuncSetAttribute(xin_mma,
                         cudaFuncAttributeMaxDynamicSharedMemorySize, SMEMA);

    init_h_tc<<<256, 256>>>(hidden);
    uprep_bf<<<24576, 256>>>(Umat);
    wprep_bf<<<6144, 256>>>(W);
    embprep_bf<<<8192, 256>>>(x, E);

    dim3 gridA(U3_ / 128, M_ / 128);   // (24, 64)
    xin_mma<<<gridA, 256, SMEMA>>>(bias);

    gru_scan<<<NBLK2, 256, SMEMSZ>>>(bias, out);
}

// round 13
// speedup vs baseline: 1.6967x; 1.2394x over previous
#include <cuda_runtime.h>
#include <cuda_bf16.h>
#include <cuda_fp16.h>
#include <math.h>
#include <stdint.h>

typedef unsigned int u32;
typedef unsigned short u16;

#define B_     64
#define T_     128
#define EMB_   256
#define UNITS_ 1024
#define U3_    3072
#define M_     8192

#define NBLK2  128          // persistent scan blocks; block owns 8 units
// scan smem layout (bytes)
#define USTR   2064         // U row stride: 2048 data + 16 pad
#define HOFF   99072        // 48 * 2064
#define HSZ    9216         // H tile: 64 rows (fp16 hi only) x 144
#define REDOFF 154368       // HOFF + 6*HSZ  (3-buffer x 2 groups)
#define SMEMSZ 160512       // REDOFF + 6144

// phase-A smem: 2 bufs x (A 256rowsx144 + B 256rowsx144)
#define ABUF   73728
#define SMEMA  147456

// ---- device-global scratch (alloc-free rule) ----
__device__ float g_xin[(size_t)M_ * U3_];             // [(t*64+b)*3072 + n]
__device__ float g_hF[2][B_ * UNITS_];                // fp32 h ping-pong [b][u]
__device__ u16 g_Hf16[2][B_][UNITS_];                 // fp16(h) [sel][b][u]
__device__ u16 g_Ubf[(size_t)NBLK2 * 2 * 24 * UNITS_];// [g][p][n=24][k] fp16 hi/lo
__device__ u16 g_Ebf[(size_t)2 * M_ * EMB_];          // [p][m'][k] gathered emb bf16
__device__ u16 g_Wbf[(size_t)2 * U3_ * EMB_];         // [p][n][k] bf16
// flat barrier state (monotonic counters)
__device__ unsigned g_barcnt;
__device__ unsigned g_bargen;

__device__ __forceinline__ u32 s2u(const void* p) {
    u32 r;
    asm("{ .reg .u64 t; cvta.to.shared.u64 t, %1; cvt.u32.u64 %0, t; }"
        : "=r"(r) : "l"(p));
    return r;
}
__device__ __forceinline__ void cpa_cg(u32 s, const void* g) {
    asm volatile("cp.async.cg.shared.global [%0], [%1], 16;" :: "r"(s), "l"(g));
}
__device__ __forceinline__ void cpa_ca(u32 s, const void* g) {
    asm volatile("cp.async.ca.shared.global [%0], [%1], 16;" :: "r"(s), "l"(g));
}
__device__ __forceinline__ void ldmx4(u32 addr, u32 r[4]) {
    asm volatile("ldmatrix.sync.aligned.m8n8.x4.shared.b16 {%0,%1,%2,%3}, [%4];"
                 : "=r"(r[0]), "=r"(r[1]), "=r"(r[2]), "=r"(r[3]) : "r"(addr));
}
__device__ __forceinline__ void ldmx2(u32 addr, u32 r[2]) {
    asm volatile("ldmatrix.sync.aligned.m8n8.x2.shared.b16 {%0,%1}, [%2];"
                 : "=r"(r[0]), "=r"(r[1]) : "r"(addr));
}
// bf16 mma (phase A)
__device__ __forceinline__ void mma_bf16(float c[4], const u32 a[4], const u32 b[2]) {
    asm volatile("mma.sync.aligned.m16n8k16.row.col.f32.bf16.bf16.f32 "
                 "{%0,%1,%2,%3}, {%4,%5,%6,%7}, {%8,%9}, {%0,%1,%2,%3};"
                 : "+f"(c[0]), "+f"(c[1]), "+f"(c[2]), "+f"(c[3])
                 : "r"(a[0]), "r"(a[1]), "r"(a[2]), "r"(a[3]),
                   "r"(b[0]), "r"(b[1]));
}
// fp16 mma (scan)
__device__ __forceinline__ void mma_f16(float c[4], const u32 a[4], const u32 b[2]) {
    asm volatile("mma.sync.aligned.m16n8k16.row.col.f32.f16.f16.f32 "
                 "{%0,%1,%2,%3}, {%4,%5,%6,%7}, {%8,%9}, {%0,%1,%2,%3};"
                 : "+f"(c[0]), "+f"(c[1]), "+f"(c[2]), "+f"(c[3])
                 : "r"(a[0]), "r"(a[1]), "r"(a[2]), "r"(a[3]),
                   "r"(b[0]), "r"(b[1]));
}

// ---------------------------------------------------------------------------
__global__ void init_h_tc(const float* __restrict__ hidden) {
    int idx = blockIdx.x * 256 + threadIdx.x;   // 65536
    if (idx == 0) { g_barcnt = 0; g_bargen = 0; }
    int b = idx >> 10, u = idx & 1023;
    float v = hidden[idx];
    g_hF[0][idx] = v;
    __half h = __float2half(v);
    g_Hf16[0][b][u] = *(u16*)&h;
}

// U^T per-block rows (fp16 hi/lo): g_Ubf[((g*2+p)*24 + n)*1024 + k], n=gate*8+ul
__global__ void uprep_bf(const float* __restrict__ U) {
    size_t idx = (size_t)blockIdx.x * 256 + threadIdx.x;  // 6,291,456
    int k = idx & 1023;
    int rest = (int)(idx >> 10);
    int n = rest % 24;
    int gp = rest / 24;
    int p = gp & 1, g = gp >> 1;
    int s = n >> 3, ul = n & 7;
    float v = U[(size_t)k * U3_ + s * UNITS_ + g * 8 + ul];
    __half hi = __float2half(v);
    __half w = p ? __float2half(v - __half2float(hi)) : hi;
    g_Ubf[idx] = *(u16*)&w;
}

// W -> bf16 hi/lo, k-major per n: g_Wbf[(p*3072+n)*256+k]
__global__ void wprep_bf(const float* __restrict__ W) {
    int gid = blockIdx.x * 256 + threadIdx.x;   // 1,572,864
    int k = gid & 255;
    int n = (gid >> 8) % U3_;
    int p = gid / (U3_ * 256);
    float v = W[(size_t)k * U3_ + n];
    __nv_bfloat16 hi = __float2bfloat16(v);
    __nv_bfloat16 w = p ? __float2bfloat16(v - __bfloat162float(hi)) : hi;
    g_Wbf[gid] = *(u16*)&w;
}

// gathered embedding -> bf16 hi/lo, m' = t*64+b: g_Ebf[(p*8192+m)*256+k]
__global__ void embprep_bf(const int* __restrict__ x,
                           const float* __restrict__ E) {
    int gid = blockIdx.x * 256 + threadIdx.x;   // 2,097,152
    int k = gid & 255, m = gid >> 8;
    int b = m & 63, t = m >> 6;
    float v = E[(size_t)x[b * T_ + t] * EMB_ + k];
    __nv_bfloat16 hi = __float2bfloat16(v);
    __nv_bfloat16 lo = __float2bfloat16(v - __bfloat162float(hi));
    g_Ebf[gid] = *(u16*)&hi;
    g_Ebf[(size_t)M_ * EMB_ + gid] = *(u16*)&lo;
}

// ---------------------------------------------------------------------------
// Phase A (tensor): xin = emb @ W + b0 via split-bf16 mma.sync. (unchanged)
// ---------------------------------------------------------------------------
__global__ void __launch_bounds__(256, 1)
xin_mma(const float* __restrict__ bias) {
    extern __shared__ char sm[];
    const u32 sb = s2u(sm);
    const int tid = threadIdx.x;
    const int w = tid >> 5, lane = tid & 31;
    const int wm = w >> 2, wn = w & 3;
    const int nt0 = blockIdx.x * 128;
    const int mt0 = blockIdx.y * 128;

    float acc[4][4][4];
#pragma unroll
    for (int a = 0; a < 4; a++)
#pragma unroll
        for (int b = 0; b < 4; b++)
#pragma unroll
            for (int c = 0; c < 4; c++) acc[a][b][c] = 0.0f;

    const char* ebase = (const char*)g_Ebf;
    const char* wbase = (const char*)g_Wbf;

#define STAGE_A(cc, buf)                                                      \
    do {                                                                      \
        const int c_ = (cc);                                                  \
        const u32 d0 = sb + (buf) * ABUF;                                     \
        _Pragma("unroll")                                                     \
        for (int j = 0; j < 8; j++) {                                         \
            int o = tid + j * 256;                                            \
            int p = o >> 10, row = (o >> 3) & 127, seg = o & 7;               \
            cpa_cg(d0 + (p * 128 + row) * 144 + seg * 16,                     \
                   ebase + ((size_t)(p * M_ + mt0 + row)) * 512 +             \
                       c_ * 128 + seg * 16);                                  \
        }                                                                     \
        _Pragma("unroll")                                                     \
        for (int j = 0; j < 8; j++) {                                         \
            int o = tid + j * 256;                                            \
            int p = o >> 10, row = (o >> 3) & 127, seg = o & 7;               \
            cpa_cg(d0 + 36864 + (p * 128 + row) * 144 + seg * 16,             \
                   wbase + ((size_t)(p * U3_ + nt0 + row)) * 512 +            \
                       c_ * 128 + seg * 16);                                  \
        }                                                                     \
        asm volatile("cp.async.commit_group;");                               \
    } while (0)

    STAGE_A(0, 0);

    const u32 a_off = (u32)((wm * 64 + (lane & 15)) * 144 + (lane >> 4) * 16);
    const u32 b_off = (u32)(36864 + (wn * 32 + (lane >> 4) * 8 + (lane & 7)) * 144 +
                            ((lane >> 3) & 1) * 16);

    for (int c = 0; c < 4; c++) {
        if (c < 3) {
            asm volatile("cp.async.wait_group 0;");
            __syncthreads();
            STAGE_A(c + 1, (c + 1) & 1);
        } else {
            asm volatile("cp.async.wait_group 0;");
            __syncthreads();
        }
        const u32 d0 = sb + (c & 1) * ABUF;
#pragma unroll
        for (int ks = 0; ks < 4; ks++) {
            u32 ah[4][4], al[4][4], bh[2][4], bl[2][4];
#pragma unroll
            for (int ms = 0; ms < 4; ms++) {
                ldmx4(d0 + a_off + ms * 16 * 144 + ks * 32, ah[ms]);
                ldmx4(d0 + a_off + (128 + ms * 16) * 144 + ks * 32, al[ms]);
            }
#pragma unroll
            for (int np = 0; np < 2; np++) {
                ldmx4(d0 + b_off + np * 16 * 144 + ks * 32, bh[np]);
                ldmx4(d0 + b_off + (128 + np * 16) * 144 + ks * 32, bl[np]);
            }
#pragma unroll
            for (int ms = 0; ms < 4; ms++)
#pragma unroll
                for (int np = 0; np < 2; np++)
#pragma unroll
                    for (int hf = 0; hf < 2; hf++) {
                        float* ac = acc[ms][np * 2 + hf];
                        mma_bf16(ac, ah[ms], bh[np] + hf * 2);
                        mma_bf16(ac, ah[ms], bl[np] + hf * 2);
                        mma_bf16(ac, al[ms], bh[np] + hf * 2);
                    }
        }
        __syncthreads();
    }
#undef STAGE_A

    float bn[4][2];
#pragma unroll
    for (int ns = 0; ns < 4; ns++)
#pragma unroll
        for (int j = 0; j < 2; j++)
            bn[ns][j] = bias[nt0 + wn * 32 + ns * 8 + 2 * (lane & 3) + j];

#pragma unroll
    for (int ms = 0; ms < 4; ms++)
#pragma unroll
        for (int ns = 0; ns < 4; ns++)
#pragma unroll
            for (int i = 0; i < 2; i++)
#pragma unroll
                for (int j = 0; j < 2; j++) {
                    int m = mt0 + wm * 64 + ms * 16 + (lane >> 2) + 8 * i;
                    int n = nt0 + wn * 32 + ns * 8 + 2 * (lane & 3) + j;
                    g_xin[(size_t)m * U3_ + n] = acc[ms][ns][2 * i + j] + bn[ns][j];
                }
}

// ---------------------------------------------------------------------------
// Persistent scan: 128 blocks x 256 thr. Block g owns 8 units. U (fp16 hi/lo)
// resident in smem; h staged as single fp16 tile; 2 MMA passes:
// rec = f16(h) · (U_hi + U_lo).  Flat monotonic barrier.
// ---------------------------------------------------------------------------
__global__ void __launch_bounds__(256, 1)
gru_scan(const float* __restrict__ bias, float* __restrict__ out) {
    extern __shared__ char sm[];
    const u32 sb = s2u(sm);
    const int tid = threadIdx.x;
    const int w = tid >> 5, lane = tid & 31;
    const int mt = w & 3, gr = w >> 2;
    const int g = blockIdx.x;

    // ---- stage U slice once (48 rows x 2048B: 24 hi rows, 24 lo rows) ----
    {
        const char* usrc = (const char*)g_Ubf + (size_t)g * 98304;
#pragma unroll
        for (int j = 0; j < 24; j++) {
            int o = tid + j * 256;
            int row = o >> 7, seg = o & 127;
            cpa_ca(sb + row * USTR + seg * 16, usrc + (size_t)o * 16);
        }
        asm volatile("cp.async.commit_group;");
    }

    const u32 a_off = (u32)((mt * 16 + (lane & 15)) * 144 + (lane >> 4) * 16);
    const u32 b01 = sb + (u32)(((lane >> 4) * 8 + (lane & 7)) * USTR +
                               ((lane >> 3) & 1) * 16);
    const u32 b2  = sb + (u32)((16 + (lane & 7)) * USTR + ((lane >> 3) & 1) * 16);

    const int u0e = g * 8 + 2 * (lane & 3);
    const int b_e = mt * 16 + (lane >> 2) + 8 * gr;
    const float bz0 = bias[U3_ + u0e],              bz1 = bias[U3_ + u0e + 1];
    const float br0 = bias[U3_ + UNITS_ + u0e],     br1 = bias[U3_ + UNITS_ + u0e + 1];
    const float bh0 = bias[U3_ + 2 * UNITS_ + u0e], bh1 = bias[U3_ + 2 * UNITS_ + u0e + 1];

    float* red = (float*)(sm + REDOFF);

    for (int t = 0; t < T_; t++) {
        const int cur = t & 1, nxt = cur ^ 1;
        const char* hsrc = (const char*)&g_Hf16[cur][0][0];

        const float* xrow = &g_xin[(size_t)(t * 64 + b_e) * U3_ + u0e];
        float xz0 = __ldg(xrow), xz1 = __ldg(xrow + 1);
        float xr0 = __ldg(xrow + UNITS_), xr1 = __ldg(xrow + UNITS_ + 1);
        float xh0 = __ldg(xrow + 2 * UNITS_), xh1 = __ldg(xrow + 2 * UNITS_ + 1);
        float hp0 = g_hF[cur][b_e * UNITS_ + u0e];
        float hp1 = g_hF[cur][b_e * UNITS_ + u0e + 1];

        float acc[3][4];
#pragma unroll
        for (int i = 0; i < 3; i++)
#pragma unroll
            for (int j = 0; j < 4; j++) acc[i][j] = 0.0f;

        // H tile per chunk per group: 64 rows x 128B (fp16 h) -> 1024 cp/chunk
#define STAGE_H(cc, buf)                                                      \
    do {                                                                      \
        _Pragma("unroll")                                                     \
        for (int j = 0; j < 4; j++) {                                         \
            int o = tid + j * 256;              /* 0..1023 */                 \
            int grs = o >> 9, r = (o >> 3) & 63, seg = o & 7;                 \
            int cab = grs * 8 + (cc);                                         \
            cpa_cg(sb + HOFF + (grs * 3 + (buf)) * HSZ + r * 144 + seg * 16,  \
                   hsrc + (size_t)r * 2048 + cab * 128 + seg * 16);           \
        }                                                                     \
        asm volatile("cp.async.commit_group;");                               \
    } while (0)

        STAGE_H(0, 0);
        STAGE_H(1, 1);

        for (int c = 0; c < 8; c++) {
            if (c < 7) asm volatile("cp.async.wait_group 1;");
            else       asm volatile("cp.async.wait_group 0;");
            __syncthreads();
            if (c < 6) STAGE_H(c + 2, (c + 2) % 3);

            const int cab = gr * 8 + c;
            const u32 abase = sb + HOFF + (u32)((gr * 3 + c % 3) * HSZ) + a_off;
            const u32 koff = (u32)(cab * 128);
#pragma unroll
            for (int ks = 0; ks < 4; ks++) {
                u32 ah[4], b4h[4], b4l[4], b2h[2], b2l[2];
                const u32 ko = koff + ks * 32;
                ldmx4(abase + ks * 32, ah);
                ldmx4(b01 + ko, b4h);
                ldmx4(b01 + 24 * USTR + ko, b4l);
                ldmx2(b2 + ko, b2h);
                ldmx2(b2 + 24 * USTR + ko, b2l);
                mma_f16(acc[0], ah, b4h);     mma_f16(acc[1], ah, b4h + 2);
                mma_f16(acc[2], ah, b2h);
                mma_f16(acc[0], ah, b4l);     mma_f16(acc[1], ah, b4l + 2);
                mma_f16(acc[2], ah, b2l);
            }
        }
#undef STAGE_H

        // ---- symmetric partial exchange ----
        const int oi = gr ^ 1;
#pragma unroll
        for (int i = 0; i < 3; i++)
#pragma unroll
            for (int j = 0; j < 2; j++)
                red[(w * 32 + lane) * 6 + i * 2 + j] = acc[i][2 * oi + j];
        __syncthreads();
        const int pw = (gr ^ 1) * 4 + mt;
#pragma unroll
        for (int i = 0; i < 3; i++)
#pragma unroll
            for (int j = 0; j < 2; j++)
                acc[i][2 * gr + j] += red[(pw * 32 + lane) * 6 + i * 2 + j];

        // ---- epilogue ----
#pragma unroll
        for (int j = 0; j < 2; j++) {
            const int u = u0e + j;
            const int r = 2 * gr + j;
            const float xz = j ? xz1 : xz0, xr = j ? xr1 : xr0, xh = j ? xh1 : xh0;
            const float hprev = j ? hp1 : hp0;
            const float bz_ = j ? bz1 : bz0, br_ = j ? br1 : br0, bh_ = j ? bh1 : bh0;

            float z = 1.f / (1.f + expf(-(xz + acc[0][r] + bz_)));
            float rr = 1.f / (1.f + expf(-(xr + acc[1][r] + br_)));
            float hh = tanhf(xh + rr * (acc[2][r] + bh_));
            float hn = z * hprev + (1.f - z) * hh;

            g_hF[nxt][b_e * UNITS_ + u] = hn;
            out[(size_t)(b_e * T_ + t) * UNITS_ + u] = hn;
            __half hv = __float2half(hn);
            g_Hf16[nxt][b_e][u] = *(u16*)&hv;
            if (t == T_ - 1)
                out[(size_t)M_ * UNITS_ + (size_t)b_e * UNITS_ + u] = hn;
        }

        // ---- flat grid barrier (monotonic, acq_rel arrival) ----
        __syncthreads();
        if (tid == 0) {
            unsigned old;
            asm volatile("atom.add.acq_rel.gpu.global.u32 %0, [%1], 1;"
                         : "=r"(old) : "l"(&g_barcnt) : "memory");
            if (old == (unsigned)(NBLK2 * (t + 1) - 1)) {
                asm volatile("st.release.gpu.global.u32 [%0], %1;"
                             :: "l"(&g_bargen), "r"((unsigned)(t + 1)) : "memory");
            } else {
                unsigned v;
                do {
                    asm volatile("ld.acquire.gpu.global.u32 %0, [%1];"
                                 : "=r"(v) : "l"(&g_bargen));
                } while (v < (unsigned)(t + 1));
            }
        }
        __syncthreads();
    }
}

extern "C" void kernel_launch(void* const* d_in, const int* in_sizes, int n_in,
                              void* d_out, int out_size) {
    const int*   x      = (const int*)d_in[0];
    const float* hidden = (const float*)d_in[1];
    const float* E      = (const float*)d_in[2];
    const float* W      = (const float*)d_in[3];
    const float* Umat   = (const float*)d_in[4];
    const float* bias   = (const float*)d_in[5];
    float* out = (float*)d_out;

    cudaFuncSetAttribute(gru_scan,
                         cudaFuncAttributeMaxDynamicSharedMemorySize, SMEMSZ);
    cudaFuncSetAttribute(xin_mma,
                         cudaFuncAttributeMaxDynamicSharedMemorySize, SMEMA);

    init_h_tc<<<256, 256>>>(hidden);
    uprep_bf<<<24576, 256>>>(Umat);
    wprep_bf<<<6144, 256>>>(W);
    embprep_bf<<<8192, 256>>>(x, E);

    dim3 gridA(U3_ / 128, M_ / 128);   // (24, 64)
    xin_mma<<<gridA, 256, SMEMA>>>(bias);

    gru_scan<<<NBLK2, 256, SMEMSZ>>>(bias, out);
}

// round 14
// speedup vs baseline: 1.7856x; 1.0524x over previous
#include <cuda_runtime.h>
#include <cuda_fp16.h>
#include <math.h>
#include <stdint.h>

typedef unsigned int u32;
typedef unsigned short u16;

#define B_     64
#define T_     128
#define EMB_   256
#define UNITS_ 1024
#define U3_    3072
#define M_     8192

#define NBLK2  128          // persistent scan blocks; block owns 8 units
// scan smem layout (bytes): U 24 rows x 2064, then 6 H bufs, then red
#define USTR   2064
#define HOFF   49536        // 24 * 2064
#define HSZ    9216         // H tile: 64 rows x 144
#define REDOFF 104832       // HOFF + 6*HSZ
#define SMEMSZ 110976       // REDOFF + 6144

// phase-A smem: 2 bufs x (A 128rowsx144 + B 256rowsx144) = 2 x 55296
#define ABUF   55296
#define BOFF   18432
#define SMEMA  110592

// ---- device-global scratch (alloc-free rule) ----
__device__ float g_xin[(size_t)M_ * U3_];             // [(t*64+b)*3072 + n]
__device__ float g_hF[2][B_ * UNITS_];                // fp32 h ping-pong [b][u]
__device__ u16 g_Hf16[2][B_][UNITS_];                 // fp16(h) [sel][b][u]
__device__ u16 g_Uf16[(size_t)NBLK2 * 24 * UNITS_];   // [g][n=24][k] fp16
__device__ u16 g_Ef16[(size_t)M_ * EMB_];             // [m'][k] gathered emb fp16
__device__ u16 g_Wf16[(size_t)2 * U3_ * EMB_];        // [p][n][k] fp16 hi/lo
// flat barrier state (monotonic counters)
__device__ unsigned g_barcnt;
__device__ unsigned g_bargen;

__device__ __forceinline__ u32 s2u(const void* p) {
    u32 r;
    asm("{ .reg .u64 t; cvta.to.shared.u64 t, %1; cvt.u32.u64 %0, t; }"
        : "=r"(r) : "l"(p));
    return r;
}
__device__ __forceinline__ void cpa_cg(u32 s, const void* g) {
    asm volatile("cp.async.cg.shared.global [%0], [%1], 16;" :: "r"(s), "l"(g));
}
__device__ __forceinline__ void cpa_ca(u32 s, const void* g) {
    asm volatile("cp.async.ca.shared.global [%0], [%1], 16;" :: "r"(s), "l"(g));
}
__device__ __forceinline__ void ldmx4(u32 addr, u32 r[4]) {
    asm volatile("ldmatrix.sync.aligned.m8n8.x4.shared.b16 {%0,%1,%2,%3}, [%4];"
                 : "=r"(r[0]), "=r"(r[1]), "=r"(r[2]), "=r"(r[3]) : "r"(addr));
}
__device__ __forceinline__ void ldmx2(u32 addr, u32 r[2]) {
    asm volatile("ldmatrix.sync.aligned.m8n8.x2.shared.b16 {%0,%1}, [%2];"
                 : "=r"(r[0]), "=r"(r[1]) : "r"(addr));
}
__device__ __forceinline__ void mma_f16(float c[4], const u32 a[4], const u32 b[2]) {
    asm volatile("mma.sync.aligned.m16n8k16.row.col.f32.f16.f16.f32 "
                 "{%0,%1,%2,%3}, {%4,%5,%6,%7}, {%8,%9}, {%0,%1,%2,%3};"
                 : "+f"(c[0]), "+f"(c[1]), "+f"(c[2]), "+f"(c[3])
                 : "r"(a[0]), "r"(a[1]), "r"(a[2]), "r"(a[3]),
                   "r"(b[0]), "r"(b[1]));
}

// ---------------------------------------------------------------------------
__global__ void init_h_tc(const float* __restrict__ hidden) {
    int idx = blockIdx.x * 256 + threadIdx.x;   // 65536
    if (idx == 0) { g_barcnt = 0; g_bargen = 0; }
    int b = idx >> 10, u = idx & 1023;
    float v = hidden[idx];
    g_hF[0][idx] = v;
    __half h = __float2half(v);
    g_Hf16[0][b][u] = *(u16*)&h;
}

// U^T per-block rows (fp16): g_Uf16[(g*24 + n)*1024 + k], n = gate*8 + ul
__global__ void uprep_f16(const float* __restrict__ U) {
    size_t idx = (size_t)blockIdx.x * 256 + threadIdx.x;  // 3,145,728
    int k = idx & 1023;
    int rest = (int)(idx >> 10);
    int n = rest % 24;
    int g = rest / 24;
    int s = n >> 3, ul = n & 7;
    float v = U[(size_t)k * U3_ + s * UNITS_ + g * 8 + ul];
    __half w = __float2half(v);
    g_Uf16[idx] = *(u16*)&w;
}

// W -> fp16 hi/lo, k-major per n: g_Wf16[(p*3072+n)*256+k]
__global__ void wprep_f16(const float* __restrict__ W) {
    int gid = blockIdx.x * 256 + threadIdx.x;   // 1,572,864
    int k = gid & 255;
    int n = (gid >> 8) % U3_;
    int p = gid / (U3_ * 256);
    float v = W[(size_t)k * U3_ + n];
    __half hi = __float2half(v);
    __half w = p ? __float2half(v - __half2float(hi)) : hi;
    g_Wf16[gid] = *(u16*)&w;
}

// gathered embedding -> fp16, m' = t*64+b: g_Ef16[m*256+k]
__global__ void embprep_f16(const int* __restrict__ x,
                            const float* __restrict__ E) {
    int gid = blockIdx.x * 256 + threadIdx.x;   // 2,097,152
    int k = gid & 255, m = gid >> 8;
    int b = m & 63, t = m >> 6;
    float v = E[(size_t)x[b * T_ + t] * EMB_ + k];
    __half hv = __float2half(v);
    g_Ef16[gid] = *(u16*)&hv;
}

// ---------------------------------------------------------------------------
// Phase A (tensor): xin = emb @ W + b0.  fp16: a=f16(emb) single,
// W = hi+lo (2 passes).  Grid (24, 64) x 256 thr; warp m64 x n32.
// ---------------------------------------------------------------------------
__global__ void __launch_bounds__(256, 1)
xin_mma(const float* __restrict__ bias) {
    extern __shared__ char sm[];
    const u32 sb = s2u(sm);
    const int tid = threadIdx.x;
    const int w = tid >> 5, lane = tid & 31;
    const int wm = w >> 2, wn = w & 3;
    const int nt0 = blockIdx.x * 128;
    const int mt0 = blockIdx.y * 128;

    float acc[4][4][4];
#pragma unroll
    for (int a = 0; a < 4; a++)
#pragma unroll
        for (int b = 0; b < 4; b++)
#pragma unroll
            for (int c = 0; c < 4; c++) acc[a][b][c] = 0.0f;

    const char* ebase = (const char*)g_Ef16;
    const char* wbase = (const char*)g_Wf16;

#define STAGE_A(cc, buf)                                                      \
    do {                                                                      \
        const int c_ = (cc);                                                  \
        const u32 d0 = sb + (buf) * ABUF;                                     \
        _Pragma("unroll")                                                     \
        for (int j = 0; j < 4; j++) {            /* A: 128 rows x 128B */     \
            int o = tid + j * 256;                                            \
            int row = o >> 3, seg = o & 7;                                    \
            cpa_cg(d0 + row * 144 + seg * 16,                                 \
                   ebase + (size_t)(mt0 + row) * 512 + c_ * 128 + seg * 16);  \
        }                                                                     \
        _Pragma("unroll")                                                     \
        for (int j = 0; j < 8; j++) {            /* B: 2p x 128 rows x 128B */\
            int o = tid + j * 256;                                            \
            int p = o >> 10, row = (o >> 3) & 127, seg = o & 7;               \
            cpa_cg(d0 + BOFF + (p * 128 + row) * 144 + seg * 16,              \
                   wbase + ((size_t)(p * U3_ + nt0 + row)) * 512 +            \
                       c_ * 128 + seg * 16);                                  \
        }                                                                     \
        asm volatile("cp.async.commit_group;");                               \
    } while (0)

    STAGE_A(0, 0);

    const u32 a_off = (u32)((wm * 64 + (lane & 15)) * 144 + (lane >> 4) * 16);
    const u32 b_off = (u32)(BOFF + (wn * 32 + (lane >> 4) * 8 + (lane & 7)) * 144 +
                            ((lane >> 3) & 1) * 16);

    for (int c = 0; c < 4; c++) {
        if (c < 3) {
            asm volatile("cp.async.wait_group 0;");
            __syncthreads();
            STAGE_A(c + 1, (c + 1) & 1);
        } else {
            asm volatile("cp.async.wait_group 0;");
            __syncthreads();
        }
        const u32 d0 = sb + (c & 1) * ABUF;
#pragma unroll
        for (int ks = 0; ks < 4; ks++) {
            u32 ah[4][4], bh[2][4], bl[2][4];
#pragma unroll
            for (int ms = 0; ms < 4; ms++)
                ldmx4(d0 + a_off + ms * 16 * 144 + ks * 32, ah[ms]);
#pragma unroll
            for (int np = 0; np < 2; np++) {
                ldmx4(d0 + b_off + np * 16 * 144 + ks * 32, bh[np]);
                ldmx4(d0 + b_off + (128 + np * 16) * 144 + ks * 32, bl[np]);
            }
#pragma unroll
            for (int ms = 0; ms < 4; ms++)
#pragma unroll
                for (int np = 0; np < 2; np++)
#pragma unroll
                    for (int hf = 0; hf < 2; hf++) {
                        float* ac = acc[ms][np * 2 + hf];
                        mma_f16(ac, ah[ms], bh[np] + hf * 2);
                        mma_f16(ac, ah[ms], bl[np] + hf * 2);
                    }
        }
        __syncthreads();
    }
#undef STAGE_A

    float bn[4][2];
#pragma unroll
    for (int ns = 0; ns < 4; ns++)
#pragma unroll
        for (int j = 0; j < 2; j++)
            bn[ns][j] = bias[nt0 + wn * 32 + ns * 8 + 2 * (lane & 3) + j];

#pragma unroll
    for (int ms = 0; ms < 4; ms++)
#pragma unroll
        for (int ns = 0; ns < 4; ns++)
#pragma unroll
            for (int i = 0; i < 2; i++)
#pragma unroll
                for (int j = 0; j < 2; j++) {
                    int m = mt0 + wm * 64 + ms * 16 + (lane >> 2) + 8 * i;
                    int n = nt0 + wn * 32 + ns * 8 + 2 * (lane & 3) + j;
                    g_xin[(size_t)m * U3_ + n] = acc[ms][ns][2 * i + j] + bn[ns][j];
                }
}

// ---------------------------------------------------------------------------
// Persistent scan: 128 blocks x 256 thr. Block g owns 8 units. U fp16 single
// (48KB resident); h fp16 single tile; ONE MMA pass: rec = f16(h)·f16(U).
// Flat monotonic barrier.
// ---------------------------------------------------------------------------
__global__ void __launch_bounds__(256, 1)
gru_scan(const float* __restrict__ bias, float* __restrict__ out) {
    extern __shared__ char sm[];
    const u32 sb = s2u(sm);
    const int tid = threadIdx.x;
    const int w = tid >> 5, lane = tid & 31;
    const int mt = w & 3, gr = w >> 2;
    const int g = blockIdx.x;

    // ---- stage U slice once (24 rows x 2048B = 48KB) ----
    {
        const char* usrc = (const char*)g_Uf16 + (size_t)g * 49152;
#pragma unroll
        for (int j = 0; j < 12; j++) {
            int o = tid + j * 256;              // 0..3071
            int row = o >> 7, seg = o & 127;
            cpa_ca(sb + row * USTR + seg * 16, usrc + (size_t)o * 16);
        }
        asm volatile("cp.async.commit_group;");
    }

    const u32 a_off = (u32)((mt * 16 + (lane & 15)) * 144 + (lane >> 4) * 16);
    const u32 b01 = sb + (u32)(((lane >> 4) * 8 + (lane & 7)) * USTR +
                               ((lane >> 3) & 1) * 16);
    const u32 b2  = sb + (u32)((16 + (lane & 7)) * USTR + ((lane >> 3) & 1) * 16);

    const int u0e = g * 8 + 2 * (lane & 3);
    const int b_e = mt * 16 + (lane >> 2) + 8 * gr;
    const float bz0 = bias[U3_ + u0e],              bz1 = bias[U3_ + u0e + 1];
    const float br0 = bias[U3_ + UNITS_ + u0e],     br1 = bias[U3_ + UNITS_ + u0e + 1];
    const float bh0 = bias[U3_ + 2 * UNITS_ + u0e], bh1 = bias[U3_ + 2 * UNITS_ + u0e + 1];

    float* red = (float*)(sm + REDOFF);

    for (int t = 0; t < T_; t++) {
        const int cur = t & 1, nxt = cur ^ 1;
        const char* hsrc = (const char*)&g_Hf16[cur][0][0];

        const float* xrow = &g_xin[(size_t)(t * 64 + b_e) * U3_ + u0e];
        float xz0 = __ldg(xrow), xz1 = __ldg(xrow + 1);
        float xr0 = __ldg(xrow + UNITS_), xr1 = __ldg(xrow + UNITS_ + 1);
        float xh0 = __ldg(xrow + 2 * UNITS_), xh1 = __ldg(xrow + 2 * UNITS_ + 1);
        float hp0 = g_hF[cur][b_e * UNITS_ + u0e];
        float hp1 = g_hF[cur][b_e * UNITS_ + u0e + 1];

        float acc[3][4];
#pragma unroll
        for (int i = 0; i < 3; i++)
#pragma unroll
            for (int j = 0; j < 4; j++) acc[i][j] = 0.0f;

        // H tile per chunk per group: 64 rows x 128B fp16 -> 1024 cp/chunk
#define STAGE_H(cc, buf)                                                      \
    do {                                                                      \
        _Pragma("unroll")                                                     \
        for (int j = 0; j < 4; j++) {                                         \
            int o = tid + j * 256;              /* 0..1023 */                 \
            int grs = o >> 9, r = (o >> 3) & 63, seg = o & 7;                 \
            int cab = grs * 8 + (cc);                                         \
            cpa_cg(sb + HOFF + (grs * 3 + (buf)) * HSZ + r * 144 + seg * 16,  \
                   hsrc + (size_t)r * 2048 + cab * 128 + seg * 16);           \
        }                                                                     \
        asm volatile("cp.async.commit_group;");                               \
    } while (0)

        STAGE_H(0, 0);
        STAGE_H(1, 1);

        for (int c = 0; c < 8; c++) {
            if (c < 7) asm volatile("cp.async.wait_group 1;");
            else       asm volatile("cp.async.wait_group 0;");
            __syncthreads();
            if (c < 6) STAGE_H(c + 2, (c + 2) % 3);

            const int cab = gr * 8 + c;
            const u32 abase = sb + HOFF + (u32)((gr * 3 + c % 3) * HSZ) + a_off;
            const u32 koff = (u32)(cab * 128);
#pragma unroll
            for (int ks = 0; ks < 4; ks++) {
                u32 ah[4], b4h[4], b2h[2];
                const u32 ko = koff + ks * 32;
                ldmx4(abase + ks * 32, ah);
                ldmx4(b01 + ko, b4h);
                ldmx2(b2 + ko, b2h);
                mma_f16(acc[0], ah, b4h);
                mma_f16(acc[1], ah, b4h + 2);
                mma_f16(acc[2], ah, b2h);
            }
        }
#undef STAGE_H

        // ---- symmetric partial exchange ----
        const int oi = gr ^ 1;
#pragma unroll
        for (int i = 0; i < 3; i++)
#pragma unroll
            for (int j = 0; j < 2; j++)
                red[(w * 32 + lane) * 6 + i * 2 + j] = acc[i][2 * oi + j];
        __syncthreads();
        const int pw = (gr ^ 1) * 4 + mt;
#pragma unroll
        for (int i = 0; i < 3; i++)
#pragma unroll
            for (int j = 0; j < 2; j++)
                acc[i][2 * gr + j] += red[(pw * 32 + lane) * 6 + i * 2 + j];

        // ---- epilogue ----
#pragma unroll
        for (int j = 0; j < 2; j++) {
            const int u = u0e + j;
            const int r = 2 * gr + j;
            const float xz = j ? xz1 : xz0, xr = j ? xr1 : xr0, xh = j ? xh1 : xh0;
            const float hprev = j ? hp1 : hp0;
            const float bz_ = j ? bz1 : bz0, br_ = j ? br1 : br0, bh_ = j ? bh1 : bh0;

            float z = 1.f / (1.f + expf(-(xz + acc[0][r] + bz_)));
            float rr = 1.f / (1.f + expf(-(xr + acc[1][r] + br_)));
            float hh = tanhf(xh + rr * (acc[2][r] + bh_));
            float hn = z * hprev + (1.f - z) * hh;

            g_hF[nxt][b_e * UNITS_ + u] = hn;
            out[(size_t)(b_e * T_ + t) * UNITS_ + u] = hn;
            __half hv = __float2half(hn);
            g_Hf16[nxt][b_e][u] = *(u16*)&hv;
            if (t == T_ - 1)
                out[(size_t)M_ * UNITS_ + (size_t)b_e * UNITS_ + u] = hn;
        }

        // ---- flat grid barrier (monotonic, acq_rel arrival) ----
        __syncthreads();
        if (tid == 0) {
            unsigned old;
            asm volatile("atom.add.acq_rel.gpu.global.u32 %0, [%1], 1;"
                         : "=r"(old) : "l"(&g_barcnt) : "memory");
            if (old == (unsigned)(NBLK2 * (t + 1) - 1)) {
                asm volatile("st.release.gpu.global.u32 [%0], %1;"
                             :: "l"(&g_bargen), "r"((unsigned)(t + 1)) : "memory");
            } else {
                unsigned v;
                do {
                    asm volatile("ld.acquire.gpu.global.u32 %0, [%1];"
                                 : "=r"(v) : "l"(&g_bargen));
                } while (v < (unsigned)(t + 1));
            }
        }
        __syncthreads();
    }
}

extern "C" void kernel_launch(void* const* d_in, const int* in_sizes, int n_in,
                              void* d_out, int out_size) {
    const int*   x      = (const int*)d_in[0];
    const float* hidden = (const float*)d_in[1];
    const float* E      = (const float*)d_in[2];
    const float* W      = (const float*)d_in[3];
    const float* Umat   = (const float*)d_in[4];
    const float* bias   = (const float*)d_in[5];
    float* out = (float*)d_out;

    cudaFuncSetAttribute(gru_scan,
                         cudaFuncAttributeMaxDynamicSharedMemorySize, SMEMSZ);
    cudaFuncSetAttribute(xin_mma,
                         cudaFuncAttributeMaxDynamicSharedMemorySize, SMEMA);

    init_h_tc<<<256, 256>>>(hidden);
    uprep_f16<<<12288, 256>>>(Umat);
    wprep_f16<<<6144, 256>>>(W);
    embprep_f16<<<8192, 256>>>(x, E);

    dim3 gridA(U3_ / 128, M_ / 128);   // (24, 64)
    xin_mma<<<gridA, 256, SMEMA>>>(bias);

    gru_scan<<<NBLK2, 256, SMEMSZ>>>(bias, out);
}

// round 16
// speedup vs baseline: 2.0257x; 1.1345x over previous
#include <cuda_runtime.h>
#include <cuda_fp16.h>
#include <math.h>
#include <stdint.h>

typedef unsigned int u32;
typedef unsigned short u16;

#define B_     64
#define T_     128
#define EMB_   256
#define UNITS_ 1024
#define U3_    3072
#define M_     8192

#define NBLK2  128          // persistent scan blocks; block owns 8 units
// scan smem layout (bytes): U 24 rows x 2064, then 6 H bufs (k=128 chunks)
#define USTR   2064
#define HOFF   49536        // 24 * 2064
#define HSTR   272          // 256B data + 16 pad
#define HSZ    17408        // 64 rows x 272
#define REDOFF 153984       // HOFF + 6*HSZ
#define SMEMSZ 160128       // REDOFF + 6144

// phase-A smem: 2 bufs x (A 128rowsx144 + B 128rowsx144) = 2 x 36864
#define ABUF   36864
#define BOFF   18432
#define SMEMA  73728

// ---- device-global scratch (alloc-free rule) ----
__device__ float g_xin[(size_t)M_ * U3_];             // [(t*64+b)*3072 + n]
__device__ float g_hF[2][B_ * UNITS_];                // fp32 h ping-pong [b][u]
__device__ u16 g_Hf16[2][B_][UNITS_];                 // fp16(h) [sel][b][u]
__device__ u16 g_Uf16[(size_t)NBLK2 * 24 * UNITS_];   // [g][n=24][k] fp16
__device__ u16 g_Ef16[(size_t)M_ * EMB_];             // [m'][k] gathered emb fp16
__device__ u16 g_Wf16[(size_t)U3_ * EMB_];            // [n][k] fp16
// flat barrier state (monotonic counters)
__device__ unsigned g_barcnt;
__device__ unsigned g_bargen;

__device__ __forceinline__ u32 s2u(const void* p) {
    u32 r;
    asm("{ .reg .u64 t; cvta.to.shared.u64 t, %1; cvt.u32.u64 %0, t; }"
        : "=r"(r) : "l"(p));
    return r;
}
__device__ __forceinline__ void cpa_cg(u32 s, const void* g) {
    asm volatile("cp.async.cg.shared.global [%0], [%1], 16;" :: "r"(s), "l"(g));
}
__device__ __forceinline__ void cpa_ca(u32 s, const void* g) {
    asm volatile("cp.async.ca.shared.global [%0], [%1], 16;" :: "r"(s), "l"(g));
}
__device__ __forceinline__ void ldmx4(u32 addr, u32 r[4]) {
    asm volatile("ldmatrix.sync.aligned.m8n8.x4.shared.b16 {%0,%1,%2,%3}, [%4];"
                 : "=r"(r[0]), "=r"(r[1]), "=r"(r[2]), "=r"(r[3]) : "r"(addr));
}
__device__ __forceinline__ void ldmx2(u32 addr, u32 r[2]) {
    asm volatile("ldmatrix.sync.aligned.m8n8.x2.shared.b16 {%0,%1}, [%2];"
                 : "=r"(r[0]), "=r"(r[1]) : "r"(addr));
}
__device__ __forceinline__ void mma_f16(float c[4], const u32 a[4], const u32 b[2]) {
    asm volatile("mma.sync.aligned.m16n8k16.row.col.f32.f16.f16.f32 "
                 "{%0,%1,%2,%3}, {%4,%5,%6,%7}, {%8,%9}, {%0,%1,%2,%3};"
                 : "+f"(c[0]), "+f"(c[1]), "+f"(c[2]), "+f"(c[3])
                 : "r"(a[0]), "r"(a[1]), "r"(a[2]), "r"(a[3]),
                   "r"(b[0]), "r"(b[1]));
}

// ---------------------------------------------------------------------------
__global__ void init_h_tc(const float* __restrict__ hidden) {
    int idx = blockIdx.x * 256 + threadIdx.x;   // 65536
    if (idx == 0) { g_barcnt = 0; g_bargen = 0; }
    int b = idx >> 10, u = idx & 1023;
    float v = hidden[idx];
    g_hF[0][idx] = v;
    __half h = __float2half(v);
    g_Hf16[0][b][u] = *(u16*)&h;
}

// U^T per-block rows (fp16): g_Uf16[(g*24 + n)*1024 + k], n = gate*8 + ul
__global__ void uprep_f16(const float* __restrict__ U) {
    size_t idx = (size_t)blockIdx.x * 256 + threadIdx.x;  // 3,145,728
    int k = idx & 1023;
    int rest = (int)(idx >> 10);
    int n = rest % 24;
    int g = rest / 24;
    int s = n >> 3, ul = n & 7;
    float v = U[(size_t)k * U3_ + s * UNITS_ + g * 8 + ul];
    __half w = __float2half(v);
    g_Uf16[idx] = *(u16*)&w;
}

// W -> fp16 (single), k-major per n: g_Wf16[n*256+k]
__global__ void wprep_f16(const float* __restrict__ W) {
    int gid = blockIdx.x * 256 + threadIdx.x;   // 786,432
    int k = gid & 255;
    int n = gid >> 8;
    float v = W[(size_t)k * U3_ + n];
    __half w = __float2half(v);
    g_Wf16[gid] = *(u16*)&w;
}

// gathered embedding -> fp16, m' = t*64+b: g_Ef16[m*256+k]
__global__ void embprep_f16(const int* __restrict__ x,
                            const float* __restrict__ E) {
    int gid = blockIdx.x * 256 + threadIdx.x;   // 2,097,152
    int k = gid & 255, m = gid >> 8;
    int b = m & 63, t = m >> 6;
    float v = E[(size_t)x[b * T_ + t] * EMB_ + k];
    __half hv = __float2half(v);
    g_Ef16[gid] = *(u16*)&hv;
}

// ---------------------------------------------------------------------------
// Phase A (tensor): xin = emb @ W + b0, single-pass fp16.
// Grid (24, 64) x 256 thr; warp m64 x n32.
// ---------------------------------------------------------------------------
__global__ void __launch_bounds__(256, 1)
xin_mma(const float* __restrict__ bias) {
    extern __shared__ char sm[];
    const u32 sb = s2u(sm);
    const int tid = threadIdx.x;
    const int w = tid >> 5, lane = tid & 31;
    const int wm = w >> 2, wn = w & 3;
    const int nt0 = blockIdx.x * 128;
    const int mt0 = blockIdx.y * 128;

    float acc[4][4][4];
#pragma unroll
    for (int a = 0; a < 4; a++)
#pragma unroll
        for (int b = 0; b < 4; b++)
#pragma unroll
            for (int c = 0; c < 4; c++) acc[a][b][c] = 0.0f;

    const char* ebase = (const char*)g_Ef16;
    const char* wbase = (const char*)g_Wf16;

#define STAGE_A(cc, buf)                                                      \
    do {                                                                      \
        const int c_ = (cc);                                                  \
        const u32 d0 = sb + (buf) * ABUF;                                     \
        _Pragma("unroll")                                                     \
        for (int j = 0; j < 4; j++) {            /* A: 128 rows x 128B */     \
            int o = tid + j * 256;                                            \
            int row = o >> 3, seg = o & 7;                                    \
            cpa_cg(d0 + row * 144 + seg * 16,                                 \
                   ebase + (size_t)(mt0 + row) * 512 + c_ * 128 + seg * 16);  \
        }                                                                     \
        _Pragma("unroll")                                                     \
        for (int j = 0; j < 4; j++) {            /* B: 128 rows x 128B */     \
            int o = tid + j * 256;                                            \
            int row = o >> 3, seg = o & 7;                                    \
            cpa_cg(d0 + BOFF + row * 144 + seg * 16,                          \
                   wbase + (size_t)(nt0 + row) * 512 + c_ * 128 + seg * 16);  \
        }                                                                     \
        asm volatile("cp.async.commit_group;");                               \
    } while (0)

    STAGE_A(0, 0);

    const u32 a_off = (u32)((wm * 64 + (lane & 15)) * 144 + (lane >> 4) * 16);
    const u32 b_off = (u32)(BOFF + (wn * 32 + (lane >> 4) * 8 + (lane & 7)) * 144 +
                            ((lane >> 3) & 1) * 16);

    for (int c = 0; c < 4; c++) {
        if (c < 3) {
            asm volatile("cp.async.wait_group 0;");
            __syncthreads();
            STAGE_A(c + 1, (c + 1) & 1);
        } else {
            asm volatile("cp.async.wait_group 0;");
            __syncthreads();
        }
        const u32 d0 = sb + (c & 1) * ABUF;
#pragma unroll
        for (int ks = 0; ks < 4; ks++) {
            u32 ah[4][4], bh[2][4];
#pragma unroll
            for (int ms = 0; ms < 4; ms++)
                ldmx4(d0 + a_off + ms * 16 * 144 + ks * 32, ah[ms]);
#pragma unroll
            for (int np = 0; np < 2; np++)
                ldmx4(d0 + b_off + np * 16 * 144 + ks * 32, bh[np]);
#pragma unroll
            for (int ms = 0; ms < 4; ms++)
#pragma unroll
                for (int np = 0; np < 2; np++)
#pragma unroll
                    for (int hf = 0; hf < 2; hf++)
                        mma_f16(acc[ms][np * 2 + hf], ah[ms], bh[np] + hf * 2);
        }
        __syncthreads();
    }
#undef STAGE_A

    float bn[4][2];
#pragma unroll
    for (int ns = 0; ns < 4; ns++)
#pragma unroll
        for (int j = 0; j < 2; j++)
            bn[ns][j] = bias[nt0 + wn * 32 + ns * 8 + 2 * (lane & 3) + j];

#pragma unroll
    for (int ms = 0; ms < 4; ms++)
#pragma unroll
        for (int ns = 0; ns < 4; ns++)
#pragma unroll
            for (int i = 0; i < 2; i++)
#pragma unroll
                for (int j = 0; j < 2; j++) {
                    int m = mt0 + wm * 64 + ms * 16 + (lane >> 2) + 8 * i;
                    int n = nt0 + wn * 32 + ns * 8 + 2 * (lane & 3) + j;
                    g_xin[(size_t)m * U3_ + n] = acc[ms][ns][2 * i + j] + bn[ns][j];
                }
}

// ---------------------------------------------------------------------------
// Persistent scan: 128 blocks x 256 thr. Block g owns 8 units. U fp16 single
// (48KB resident); h fp16 tile, chunk k=128, 4 loop iterations per step.
// Flat monotonic barrier.
// ---------------------------------------------------------------------------
__global__ void __launch_bounds__(256, 1)
gru_scan(const float* __restrict__ bias, float* __restrict__ out) {
    extern __shared__ char sm[];
    const u32 sb = s2u(sm);
    const int tid = threadIdx.x;
    const int w = tid >> 5, lane = tid & 31;
    const int mt = w & 3, gr = w >> 2;
    const int g = blockIdx.x;

    // ---- stage U slice once (24 rows x 2048B = 48KB) ----
    {
        const char* usrc = (const char*)g_Uf16 + (size_t)g * 49152;
#pragma unroll
        for (int j = 0; j < 12; j++) {
            int o = tid + j * 256;              // 0..3071
            int row = o >> 7, seg = o & 127;
            cpa_ca(sb + row * USTR + seg * 16, usrc + (size_t)o * 16);
        }
        asm volatile("cp.async.commit_group;");
    }

    const u32 a_off = (u32)((mt * 16 + (lane & 15)) * HSTR + (lane >> 4) * 16);
    const u32 b01 = sb + (u32)(((lane >> 4) * 8 + (lane & 7)) * USTR +
                               ((lane >> 3) & 1) * 16);
    const u32 b2  = sb + (u32)((16 + (lane & 7)) * USTR + ((lane >> 3) & 1) * 16);

    const int u0e = g * 8 + 2 * (lane & 3);
    const int b_e = mt * 16 + (lane >> 2) + 8 * gr;
    const float bz0 = bias[U3_ + u0e],              bz1 = bias[U3_ + u0e + 1];
    const float br0 = bias[U3_ + UNITS_ + u0e],     br1 = bias[U3_ + UNITS_ + u0e + 1];
    const float bh0 = bias[U3_ + 2 * UNITS_ + u0e], bh1 = bias[U3_ + 2 * UNITS_ + u0e + 1];

    float* red = (float*)(sm + REDOFF);

    for (int t = 0; t < T_; t++) {
        const int cur = t & 1, nxt = cur ^ 1;
        const char* hsrc = (const char*)&g_Hf16[cur][0][0];

        const float* xrow = &g_xin[(size_t)(t * 64 + b_e) * U3_ + u0e];
        float xz0 = __ldg(xrow), xz1 = __ldg(xrow + 1);
        float xr0 = __ldg(xrow + UNITS_), xr1 = __ldg(xrow + UNITS_ + 1);
        float xh0 = __ldg(xrow + 2 * UNITS_), xh1 = __ldg(xrow + 2 * UNITS_ + 1);
        float hp0 = g_hF[cur][b_e * UNITS_ + u0e];
        float hp1 = g_hF[cur][b_e * UNITS_ + u0e + 1];

        float acc[3][4];
#pragma unroll
        for (int i = 0; i < 3; i++)
#pragma unroll
            for (int j = 0; j < 4; j++) acc[i][j] = 0.0f;

        // H tile per chunk per group: 64 rows x 256B fp16 (k=128) -> 2048 cp
#define STAGE_H(cc, buf)                                                      \
    do {                                                                      \
        _Pragma("unroll")                                                     \
        for (int j = 0; j < 8; j++) {                                         \
            int o = tid + j * 256;              /* 0..2047 */                 \
            int grs = o >> 10, r = (o >> 4) & 63, seg = o & 15;               \
            cpa_cg(sb + HOFF + (grs * 3 + (buf)) * HSZ + r * HSTR + seg * 16, \
                   hsrc + (size_t)r * 2048 + grs * 1024 + (cc) * 256 +        \
                       seg * 16);                                             \
        }                                                                     \
        asm volatile("cp.async.commit_group;");                               \
    } while (0)

        STAGE_H(0, 0);
        STAGE_H(1, 1);

        for (int c = 0; c < 4; c++) {
            if (c < 3) asm volatile("cp.async.wait_group 1;");
            else       asm volatile("cp.async.wait_group 0;");
            __syncthreads();
            if (c < 2) STAGE_H(c + 2, (c + 2) % 3);   // buffers 2, then 0

            const u32 abase = sb + HOFF + (u32)((gr * 3 + c % 3) * HSZ) + a_off;
            const u32 koff = (u32)(gr * 1024 + c * 256);
#pragma unroll
            for (int ks = 0; ks < 8; ks++) {
                u32 ah[4], b4h[4], b2h[2];
                const u32 ko = koff + ks * 32;
                ldmx4(abase + ks * 32, ah);
                ldmx4(b01 + ko, b4h);
                ldmx2(b2 + ko, b2h);
                mma_f16(acc[0], ah, b4h);
                mma_f16(acc[1], ah, b4h + 2);
                mma_f16(acc[2], ah, b2h);
            }
        }
#undef STAGE_H

        // ---- symmetric partial exchange ----
        const int oi = gr ^ 1;
#pragma unroll
        for (int i = 0; i < 3; i++)
#pragma unroll
            for (int j = 0; j < 2; j++)
                red[(w * 32 + lane) * 6 + i * 2 + j] = acc[i][2 * oi + j];
        __syncthreads();
        const int pw = (gr ^ 1) * 4 + mt;
#pragma unroll
        for (int i = 0; i < 3; i++)
#pragma unroll
            for (int j = 0; j < 2; j++)
                acc[i][2 * gr + j] += red[(pw * 32 + lane) * 6 + i * 2 + j];

        // ---- epilogue ----
#pragma unroll
        for (int j = 0; j < 2; j++) {
            const int u = u0e + j;
            const int r = 2 * gr + j;
            const float xz = j ? xz1 : xz0, xr = j ? xr1 : xr0, xh = j ? xh1 : xh0;
            const float hprev = j ? hp1 : hp0;
            const float bz_ = j ? bz1 : bz0, br_ = j ? br1 : br0, bh_ = j ? bh1 : bh0;

            float z = 1.f / (1.f + expf(-(xz + acc[0][r] + bz_)));
            float rr = 1.f / (1.f + expf(-(xr + acc[1][r] + br_)));
            float hh = tanhf(xh + rr * (acc[2][r] + bh_));
            float hn = z * hprev + (1.f - z) * hh;

            g_hF[nxt][b_e * UNITS_ + u] = hn;
            out[(size_t)(b_e * T_ + t) * UNITS_ + u] = hn;
            __half hv = __float2half(hn);
            g_Hf16[nxt][b_e][u] = *(u16*)&hv;
            if (t == T_ - 1)
                out[(size_t)M_ * UNITS_ + (size_t)b_e * UNITS_ + u] = hn;
        }

        // ---- flat grid barrier (monotonic, acq_rel arrival) ----
        __syncthreads();
        if (tid == 0) {
            unsigned old;
            asm volatile("atom.add.acq_rel.gpu.global.u32 %0, [%1], 1;"
                         : "=r"(old) : "l"(&g_barcnt) : "memory");
            if (old == (unsigned)(NBLK2 * (t + 1) - 1)) {
                asm volatile("st.release.gpu.global.u32 [%0], %1;"
                             :: "l"(&g_bargen), "r"((unsigned)(t + 1)) : "memory");
            } else {
                unsigned v;
                do {
                    asm volatile("ld.acquire.gpu.global.u32 %0, [%1];"
                                 : "=r"(v) : "l"(&g_bargen));
                } while (v < (unsigned)(t + 1));
            }
        }
        __syncthreads();
    }
}

extern "C" void kernel_launch(void* const* d_in, const int* in_sizes, int n_in,
                              void* d_out, int out_size) {
    const int*   x      = (const int*)d_in[0];
    const float* hidden = (const float*)d_in[1];
    const float* E      = (const float*)d_in[2];
    const float* W      = (const float*)d_in[3];
    const float* Umat   = (const float*)d_in[4];
    const float* bias   = (const float*)d_in[5];
    float* out = (float*)d_out;

    cudaFuncSetAttribute(gru_scan,
                         cudaFuncAttributeMaxDynamicSharedMemorySize, SMEMSZ);
    cudaFuncSetAttribute(xin_mma,
                         cudaFuncAttributeMaxDynamicSharedMemorySize, SMEMA);

    init_h_tc<<<256, 256>>>(hidden);
    uprep_f16<<<12288, 256>>>(Umat);
    wprep_f16<<<3072, 256>>>(W);
    embprep_f16<<<8192, 256>>>(x, E);

    dim3 gridA(U3_ / 128, M_ / 128);   // (24, 64)
    xin_mma<<<gridA, 256, SMEMA>>>(bias);

    gru_scan<<<NBLK2, 256, SMEMSZ>>>(bias, out);
}